// round 9
// baseline (speedup 1.0000x reference)
#include <cuda_runtime.h>
#include <math.h>
#include <cstdint>

#define BB  512
#define SSL 128
#define HH  192
#define VV  256
#define PP  64
#define PHD 16
#define BT  4
#define NTH 384

typedef unsigned long long u64;

__device__ float TB_SEL[VV][PP];    // emb @ sel_W[0:192]
__device__ float TB_BIND[VV][HH];   // emb @ bind_W1[0:192]
__device__ float M1[PP][HH];        // patch_values @ bind_W1[192:384]
__device__ float M2[PP][HH];        // patch_values @ succ_W1[192:384]
__device__ float M3[PHD][HH];       // phase_embed  @ succ_W1[384:576]
__device__ float ROUT_T[PHD][2 * HH]; // router_W transposed: [col][row]

struct SMLayout {
    float prevb[HH][BT];
    float sec  [HH][BT];
    float succ [HH][BT];
    float htmp [HH][BT];
    float tbind[HH][BT];
    float tsel [PP][BT];
    float pwb  [PP][BT];
    float phwb [PHD][BT];
    float rlog [PHD][BT];
    float gatev[BT];
    float lnmean[BT], lnrstd[BT];
    int   sidx[BT][SSL];
};

__device__ __forceinline__ float gelu_exact(float x) {
    return 0.5f * x * (1.0f + erff(x * 0.70710678118654752440f));
}
__device__ __forceinline__ float sigmoidf_(float x) {
    return 1.0f / (1.0f + expf(-x));
}
__device__ __forceinline__ u64 ffma2u(u64 a, u64 b, u64 c) {
    u64 d;
    asm("fma.rn.f32x2 %0, %1, %2, %3;" : "=l"(d) : "l"(a), "l"(b), "l"(c));
    return d;
}
__device__ __forceinline__ u64 add2(u64 a, u64 b) {
    u64 d;
    asm("add.rn.f32x2 %0, %1, %2;" : "=l"(d) : "l"(a), "l"(b));
    return d;
}
__device__ __forceinline__ u64 dup2(float w) {
    u64 d;
    asm("mov.b64 %0, {%1, %1};" : "=l"(d) : "f"(w));
    return d;
}

// K-interleaved segment: rows r0 + k*ST. 4 cols x 4 rows FFMA2 tile.
template<int NIT, int ST>
__device__ __forceinline__ void seg2s(
    u64 (&ac)[4][2],
    const float (*__restrict__ X)[BT], const float* __restrict__ W,
    int r0, int Ns, int c0)
{
    #pragma unroll 8
    for (int k = 0; k < NIT; ++k) {
        int row = r0 + k * ST;
        float4 w = *(const float4*)(W + (size_t)row * Ns + c0);
        ulonglong2 x = *(const ulonglong2*)&X[row][0];
        u64 w0 = dup2(w.x), w1 = dup2(w.y), w2 = dup2(w.z), w3 = dup2(w.w);
        ac[0][0] = ffma2u(w0, x.x, ac[0][0]); ac[0][1] = ffma2u(w0, x.y, ac[0][1]);
        ac[1][0] = ffma2u(w1, x.x, ac[1][0]); ac[1][1] = ffma2u(w1, x.y, ac[1][1]);
        ac[2][0] = ffma2u(w2, x.x, ac[2][0]); ac[2][1] = ffma2u(w2, x.y, ac[2][1]);
        ac[3][0] = ffma2u(w3, x.x, ac[3][0]); ac[3][1] = ffma2u(w3, x.y, ac[3][1]);
    }
}

// butterfly-reduce ac over low lane bits (masks 1..MMAX)
#define BFLY(ac, MMAX)                                                         \
    _Pragma("unroll")                                                          \
    for (int m = 1; m <= (MMAX); m <<= 1) {                                    \
        _Pragma("unroll")                                                      \
        for (int c = 0; c < 4; ++c) {                                          \
            ac[c][0] = add2(ac[c][0], __shfl_xor_sync(0xffffffffu, ac[c][0], m)); \
            ac[c][1] = add2(ac[c][1], __shfl_xor_sync(0xffffffffu, ac[c][1], m)); \
        }                                                                      \
    }

// ---------------- precompute kernel ----------------------------------------
__global__ void precompute_kernel(
    const float* __restrict__ emb, const float* __restrict__ sel_W,
    const float* __restrict__ bind_W1, const float* __restrict__ succ_W1,
    const float* __restrict__ patch_values, const float* __restrict__ phase_embed,
    const float* __restrict__ router_W)
{
    int idx = blockIdx.x * blockDim.x + threadIdx.x;
    const int N0 = VV * PP;
    const int N1 = N0 + VV * HH;
    const int N2 = N1 + PP * HH;
    const int N3 = N2 + PP * HH;
    const int N4 = N3 + PHD * HH;
    const int N5 = N4 + PHD * 2 * HH;
    if (idx < N0) {
        int v = idx / PP, c = idx % PP;
        float acc = 0.f;
        for (int k = 0; k < HH; ++k) acc = fmaf(emb[v * HH + k], sel_W[k * PP + c], acc);
        TB_SEL[v][c] = acc;
    } else if (idx < N1) {
        int i = idx - N0, v = i / HH, c = i % HH;
        float acc = 0.f;
        for (int k = 0; k < HH; ++k) acc = fmaf(emb[v * HH + k], bind_W1[k * HH + c], acc);
        TB_BIND[v][c] = acc;
    } else if (idx < N2) {
        int i = idx - N1, p = i / HH, c = i % HH;
        float acc = 0.f;
        for (int k = 0; k < HH; ++k) acc = fmaf(patch_values[p * HH + k], bind_W1[(HH + k) * HH + c], acc);
        M1[p][c] = acc;
    } else if (idx < N3) {
        int i = idx - N2, p = i / HH, c = i % HH;
        float acc = 0.f;
        for (int k = 0; k < HH; ++k) acc = fmaf(patch_values[p * HH + k], succ_W1[(HH + k) * HH + c], acc);
        M2[p][c] = acc;
    } else if (idx < N4) {
        int i = idx - N3, q = i / HH, c = i % HH;
        float acc = 0.f;
        for (int k = 0; k < HH; ++k) acc = fmaf(phase_embed[q * HH + k], succ_W1[(2 * HH + k) * HH + c], acc);
        M3[q][c] = acc;
    } else if (idx < N5) {
        int i = idx - N4, c = i / (2 * HH), r = i % (2 * HH);
        ROUT_T[c][r] = router_W[r * PHD + c];
    }
}

// ---------------- decoder kernel -------------------------------------------
#define DROWS 64
#define DTH   512
__global__ __launch_bounds__(DTH, 1)
void decoder_kernel(const float* __restrict__ hidden,
                    const float* __restrict__ dec_W,
                    float* __restrict__ logits)
{
    __shared__ float hid[HH][DROWS];
    const int t = threadIdx.x;
    const size_t row0 = (size_t)blockIdx.x * DROWS;

    for (int i = t; i < DROWS * (HH / 4); i += DTH) {
        int r = i / (HH / 4), kq = i % (HH / 4);
        float4 v = *(const float4*)&hidden[(row0 + r) * HH + 4 * kq];
        hid[4 * kq + 0][r] = v.x; hid[4 * kq + 1][r] = v.y;
        hid[4 * kq + 2][r] = v.z; hid[4 * kq + 3][r] = v.w;
    }
    __syncthreads();

    const int cg = t % 64, rg = t / 64;
    const int c0 = 4 * cg, r0 = 8 * rg;
    u64 ac[4][4] = {};
    #pragma unroll 4
    for (int k = 0; k < HH; ++k) {
        float4 w = *(const float4*)&dec_W[(size_t)k * VV + c0];
        ulonglong2 xa = *(const ulonglong2*)&hid[k][r0];
        ulonglong2 xb = *(const ulonglong2*)&hid[k][r0 + 4];
        u64 w0 = dup2(w.x), w1 = dup2(w.y), w2 = dup2(w.z), w3 = dup2(w.w);
        ac[0][0] = ffma2u(w0, xa.x, ac[0][0]); ac[0][1] = ffma2u(w0, xa.y, ac[0][1]);
        ac[0][2] = ffma2u(w0, xb.x, ac[0][2]); ac[0][3] = ffma2u(w0, xb.y, ac[0][3]);
        ac[1][0] = ffma2u(w1, xa.x, ac[1][0]); ac[1][1] = ffma2u(w1, xa.y, ac[1][1]);
        ac[1][2] = ffma2u(w1, xb.x, ac[1][2]); ac[1][3] = ffma2u(w1, xb.y, ac[1][3]);
        ac[2][0] = ffma2u(w2, xa.x, ac[2][0]); ac[2][1] = ffma2u(w2, xa.y, ac[2][1]);
        ac[2][2] = ffma2u(w2, xb.x, ac[2][2]); ac[2][3] = ffma2u(w2, xb.y, ac[2][3]);
        ac[3][0] = ffma2u(w3, xa.x, ac[3][0]); ac[3][1] = ffma2u(w3, xa.y, ac[3][1]);
        ac[3][2] = ffma2u(w3, xb.x, ac[3][2]); ac[3][3] = ffma2u(w3, xb.y, ac[3][3]);
    }
    #pragma unroll
    for (int p = 0; p < 4; ++p) {
        #pragma unroll
        for (int j = 0; j < 2; ++j) {
            int r = r0 + 2 * p + j;
            float4 o;
            o.x = ((float*)&ac[0][p])[j]; o.y = ((float*)&ac[1][p])[j];
            o.z = ((float*)&ac[2][p])[j]; o.w = ((float*)&ac[3][p])[j];
            *(float4*)&logits[(row0 + r) * VV + c0] = o;
        }
    }
}

// ---------------- main recurrence kernel -----------------------------------
__device__ __forceinline__ void gather_tables(SMLayout* s, int t, int st) {
    int id0 = s->sidx[0][st], id1 = s->sidx[1][st],
        id2 = s->sidx[2][st], id3 = s->sidx[3][st];
    if (t < PP * BT) {
        int c = t % PP, r = t / PP;
        int id = (r == 0) ? id0 : (r == 1) ? id1 : (r == 2) ? id2 : id3;
        s->tsel[c][r] = TB_SEL[id][c];
    }
    for (int i = t; i < HH * BT; i += NTH) {
        int c = i % HH, r = i / HH;
        int id = (r == 0) ? id0 : (r == 1) ? id1 : (r == 2) ? id2 : id3;
        s->tbind[c][r] = TB_BIND[id][c];
    }
}

__global__ __launch_bounds__(NTH, 1)
void spike_recurrence_kernel(
    const int*   __restrict__ input_ids,
    const float* __restrict__ sel_W,  const float* __restrict__ sel_b,
    const float* __restrict__ bind_W1, const float* __restrict__ bind_b1,
    const float* __restrict__ bind_W2, const float* __restrict__ bind_b2,
    const float* __restrict__ router_b,
    const float* __restrict__ succ_W1, const float* __restrict__ succ_b1,
    const float* __restrict__ succ_W2, const float* __restrict__ succ_b2,
    const float* __restrict__ gate_W1, const float* __restrict__ gate_b1,
    const float* __restrict__ gate_W2, const float* __restrict__ gate_b2,
    const float* __restrict__ ln_g,   const float* __restrict__ ln_b,
    float* __restrict__ out)
{
    __shared__ SMLayout sm;
    SMLayout* s = &sm;

    const int t    = threadIdx.x;
    const int lane = t & 31;
    const int warp = t >> 5;
    const int bbase = blockIdx.x * BT;

    for (int i = t; i < BT * SSL; i += NTH) {
        int r = i / SSL, ss = i % SSL;
        s->sidx[r][ss] = input_ids[(bbase + r) * SSL + ss];
    }
    if (t < HH) *(float4*)&s->prevb[t][0] = make_float4(0.f, 0.f, 0.f, 0.f);
    __syncthreads();
    gather_tables(s, t, 0);
    __syncthreads();

    const size_t OFF_HID = (size_t)BB * SSL * VV;
    const size_t OFF_PW  = OFF_HID + (size_t)BB * SSL * HH;
    const size_t OFF_PHW = OFF_PW  + (size_t)BB * SSL * PP;
    const size_t OFF_GT  = OFF_PHW + (size_t)BB * SSL * PHD;

    const float* selWp  = sel_W  + HH * PP;               // prev rows
    const float* bindWp = bind_W1 + 2 * (size_t)HH * HH;  // prev rows
    const float* gateWp = gate_W1 + (size_t)HH * HH;      // prev rows

    for (int st = 0; st < SSL; ++st) {
        // ---- A) sel: prev @ selWp + tsel + b  (warps 0-7, P=16) ----------
        if (t < 256) {
            int g = (warp << 1) + (lane >> 4);   // 0..15
            int p = lane & 15;
            int c0 = 4 * g;
            u64 ac[4][2] = {};
            seg2s<12, 16>(ac, s->prevb, selWp, p, PP, c0);
            BFLY(ac, 8);
            int j = lane & 15;
            int q = j >> 1, sub = j & 1;
            int c = q >> 1, h = q & 1;
            float2 f; *(u64*)&f = ac[c][h];
            float v = sub ? f.y : f.x;
            int col = c0 + c, row = 2 * h + sub;
            s->pwb[col][row] = v + s->tsel[col][row] + sel_b[col];
        }
        __syncthreads();

        // ---- B) softmax over 64 (warps 0-3) -------------------------------
        if (warp < BT) {
            int r = warp;
            float v0 = s->pwb[lane][r], v1 = s->pwb[lane + 32][r];
            float m = fmaxf(v0, v1);
            #pragma unroll
            for (int o = 16; o > 0; o >>= 1) m = fmaxf(m, __shfl_xor_sync(0xffffffffu, m, o));
            float e0 = expf(v0 - m), e1 = expf(v1 - m);
            float smv = e0 + e1;
            #pragma unroll
            for (int o = 16; o > 0; o >>= 1) smv += __shfl_xor_sync(0xffffffffu, smv, o);
            float inv = 1.0f / smv;
            e0 *= inv; e1 *= inv;
            s->pwb[lane][r] = e0; s->pwb[lane + 32][r] = e1;
            size_t ob = OFF_PW + ((size_t)(bbase + r) * SSL + st) * PP;
            out[ob + lane] = e0; out[ob + lane + 32] = e1;
        }
        __syncthreads();

        // ---- C) bind1: prev@bindWp + pw@M1 + tbind -> gelu ----------------
        {
            int g = (warp << 2) + (lane >> 3);   // 0..47
            int p = lane & 7;
            int c0 = 4 * g;
            u64 ac[4][2] = {};
            seg2s<24, 8>(ac, s->prevb, bindWp,    p, HH, c0);
            seg2s<8, 8> (ac, s->pwb,   &M1[0][0], p, HH, c0);
            BFLY(ac, 4);
            int j = lane & 7, c = j >> 1, h = j & 1;
            float2 f; *(u64*)&f = ac[c][h];
            int col = c0 + c;
            float2 tv = *(const float2*)&s->tbind[col][2 * h];
            float b1 = bind_b1[col];
            f.x = gelu_exact(f.x + tv.x + b1);
            f.y = gelu_exact(f.y + tv.y + b1);
            *(float2*)&s->htmp[col][2 * h] = f;
        }
        __syncthreads();

        // ---- D) bind2 -> tanh -> sec ---------------------------------------
        {
            int g = (warp << 2) + (lane >> 3);
            int p = lane & 7;
            int c0 = 4 * g;
            u64 ac[4][2] = {};
            seg2s<24, 8>(ac, s->htmp, bind_W2, p, HH, c0);
            BFLY(ac, 4);
            int j = lane & 7, c = j >> 1, h = j & 1;
            float2 f; *(u64*)&f = ac[c][h];
            int col = c0 + c;
            float b2 = bind_b2[col];
            f.x = tanhf(f.x + b2); f.y = tanhf(f.y + b2);
            *(float2*)&s->sec[col][2 * h] = f;
        }
        __syncthreads();

        // ---- E) router: [sec,prev] @ ROUT_T (warps 0-7, scalar col) --------
        if (t < 256) {
            int col = t >> 4;          // 0..15
            int p = lane & 15;
            u64 a0 = 0ull, a1 = 0ull;
            const float* wp = &ROUT_T[col][0];
            #pragma unroll 8
            for (int k = 0; k < 12; ++k) {
                int row = p + 16 * k;
                u64 w = dup2(wp[row]);
                ulonglong2 x = *(const ulonglong2*)&s->sec[row][0];
                a0 = ffma2u(w, x.x, a0); a1 = ffma2u(w, x.y, a1);
            }
            #pragma unroll 8
            for (int k = 0; k < 12; ++k) {
                int row = p + 16 * k;
                u64 w = dup2(wp[HH + row]);
                ulonglong2 x = *(const ulonglong2*)&s->prevb[row][0];
                a0 = ffma2u(w, x.x, a0); a1 = ffma2u(w, x.y, a1);
            }
            #pragma unroll
            for (int m = 1; m <= 8; m <<= 1) {
                a0 = add2(a0, __shfl_xor_sync(0xffffffffu, a0, m));
                a1 = add2(a1, __shfl_xor_sync(0xffffffffu, a1, m));
            }
            int j = lane & 15;
            if (j < 4) {
                u64 v = (j >> 1) ? a1 : a0;
                float2 f; *(u64*)&f = v;
                s->rlog[col][j] = ((j & 1) ? f.y : f.x) + router_b[col];
            }
        }
        __syncthreads();

        // ---- F) router softmax (t<4) ---------------------------------------
        if (t < BT) {
            int r = t;
            float m = -1e30f;
            #pragma unroll
            for (int c = 0; c < PHD; ++c) m = fmaxf(m, s->rlog[c][r]);
            float smv = 0.f;
            float e[PHD];
            #pragma unroll
            for (int c = 0; c < PHD; ++c) { e[c] = expf(s->rlog[c][r] - m); smv += e[c]; }
            float inv = 1.0f / smv;
            size_t ob = OFF_PHW + ((size_t)(bbase + r) * SSL + st) * PHD;
            #pragma unroll
            for (int c = 0; c < PHD; ++c) {
                float v = e[c] * inv;
                s->phwb[c][r] = v;
                out[ob + c] = v;
            }
        }
        __syncthreads();

        // ---- G) succ1: sec@W + pw@M2 + phw@M3 -> gelu ----------------------
        {
            int g = (warp << 2) + (lane >> 3);
            int p = lane & 7;
            int c0 = 4 * g;
            u64 ac[4][2] = {};
            seg2s<24, 8>(ac, s->sec,  succ_W1,   p, HH, c0);
            seg2s<8, 8> (ac, s->pwb,  &M2[0][0], p, HH, c0);
            seg2s<2, 8> (ac, s->phwb, &M3[0][0], p, HH, c0);
            BFLY(ac, 4);
            int j = lane & 7, c = j >> 1, h = j & 1;
            float2 f; *(u64*)&f = ac[c][h];
            int col = c0 + c;
            float b1 = succ_b1[col];
            f.x = gelu_exact(f.x + b1); f.y = gelu_exact(f.y + b1);
            *(float2*)&s->htmp[col][2 * h] = f;
        }
        __syncthreads();

        // ---- H) succ2 -> tanh -> succ ---------------------------------------
        {
            int g = (warp << 2) + (lane >> 3);
            int p = lane & 7;
            int c0 = 4 * g;
            u64 ac[4][2] = {};
            seg2s<24, 8>(ac, s->htmp, succ_W2, p, HH, c0);
            BFLY(ac, 4);
            int j = lane & 7, c = j >> 1, h = j & 1;
            float2 f; *(u64*)&f = ac[c][h];
            int col = c0 + c;
            float b2 = succ_b2[col];
            f.x = tanhf(f.x + b2); f.y = tanhf(f.y + b2);
            *(float2*)&s->succ[col][2 * h] = f;
        }
        __syncthreads();

        // ---- I) gate: [succ,prev] @ gate_W1 -> gelu * w2 --------------------
        {
            int g = (warp << 2) + (lane >> 3);
            int p = lane & 7;
            int c0 = 4 * g;
            u64 ac[4][2] = {};
            seg2s<24, 8>(ac, s->succ,  gate_W1, p, HH, c0);
            seg2s<24, 8>(ac, s->prevb, gateWp,  p, HH, c0);
            BFLY(ac, 4);
            int j = lane & 7, c = j >> 1, h = j & 1;
            float2 f; *(u64*)&f = ac[c][h];
            int col = c0 + c;
            float b1 = gate_b1[col];
            float w2 = gate_W2[col];
            f.x = gelu_exact(f.x + b1) * w2;
            f.y = gelu_exact(f.y + b1) * w2;
            *(float2*)&s->htmp[col][2 * h] = f;
        }
        __syncthreads();

        // ---- J) gate row-sum + sigmoid (warps 0-3) ---------------------------
        if (warp < BT) {
            int r = warp;
            float sg = 0.f;
            #pragma unroll
            for (int j = 0; j < 6; ++j) sg += s->htmp[lane + 32 * j][r];
            #pragma unroll
            for (int o = 16; o > 0; o >>= 1) sg += __shfl_xor_sync(0xffffffffu, sg, o);
            if (lane == 0) {
                float gv = sigmoidf_(sg + gate_b2[0]);
                s->gatev[r] = gv;
                out[OFF_GT + (size_t)(bbase + r) * SSL + st] = gv;
            }
        }
        __syncthreads();

        // ---- K) LN stats with on-the-fly blend (warps 0-3) -------------------
        if (warp < BT) {
            int r = warp;
            float gv = s->gatev[r];
            float smv = 0.f, sq = 0.f;
            #pragma unroll
            for (int j = 0; j < 6; ++j) {
                int c = lane + 32 * j;
                float v = gv * s->succ[c][r] + (1.f - gv) * s->prevb[c][r];
                smv += v; sq += v * v;
            }
            #pragma unroll
            for (int o = 16; o > 0; o >>= 1) {
                smv += __shfl_xor_sync(0xffffffffu, smv, o);
                sq  += __shfl_xor_sync(0xffffffffu, sq, o);
            }
            if (lane == 0) {
                float mean = smv * (1.0f / HH);
                float var  = sq * (1.0f / HH) - mean * mean;
                s->lnmean[r] = mean;
                s->lnrstd[r] = rsqrtf(var + 1e-5f);
            }
        }
        __syncthreads();

        // ---- L) blend recompute + LN write + gather next tables ---------------
        if (t < HH) {
            float g = ln_g[t], bb = ln_b[t];
            float4 svv = *(const float4*)&s->succ[t][0];
            float4 pv  = *(const float4*)&s->prevb[t][0];
            float4 o;
            float g0 = s->gatev[0], g1 = s->gatev[1], g2 = s->gatev[2], g3 = s->gatev[3];
            float h0 = g0 * svv.x + (1.f - g0) * pv.x;
            float h1 = g1 * svv.y + (1.f - g1) * pv.y;
            float h2 = g2 * svv.z + (1.f - g2) * pv.z;
            float h3 = g3 * svv.w + (1.f - g3) * pv.w;
            o.x = (h0 - s->lnmean[0]) * s->lnrstd[0] * g + bb;
            o.y = (h1 - s->lnmean[1]) * s->lnrstd[1] * g + bb;
            o.z = (h2 - s->lnmean[2]) * s->lnrstd[2] * g + bb;
            o.w = (h3 - s->lnmean[3]) * s->lnrstd[3] * g + bb;
            *(float4*)&s->prevb[t][0] = o;
            #pragma unroll
            for (int r = 0; r < BT; ++r)
                out[OFF_HID + ((size_t)(bbase + r) * SSL + st) * HH + t] =
                    (r == 0) ? o.x : (r == 1) ? o.y : (r == 2) ? o.z : o.w;
        }
        if (st + 1 < SSL) gather_tables(s, t, st + 1);
        __syncthreads();
    }
}

extern "C" void kernel_launch(void* const* d_in, const int* in_sizes, int n_in,
                              void* d_out, int out_size) {
    const int*   input_ids    = (const int*)  d_in[0];
    const float* emb          = (const float*)d_in[1];
    const float* sel_W        = (const float*)d_in[2];
    const float* sel_b        = (const float*)d_in[3];
    const float* patch_values = (const float*)d_in[4];
    const float* bind_W1      = (const float*)d_in[5];
    const float* bind_b1      = (const float*)d_in[6];
    const float* bind_W2      = (const float*)d_in[7];
    const float* bind_b2      = (const float*)d_in[8];
    const float* phase_embed  = (const float*)d_in[9];
    const float* router_W     = (const float*)d_in[10];
    const float* router_b     = (const float*)d_in[11];
    const float* succ_W1      = (const float*)d_in[12];
    const float* succ_b1      = (const float*)d_in[13];
    const float* succ_W2      = (const float*)d_in[14];
    const float* succ_b2      = (const float*)d_in[15];
    const float* gate_W1      = (const float*)d_in[16];
    const float* gate_b1      = (const float*)d_in[17];
    const float* gate_W2      = (const float*)d_in[18];
    const float* gate_b2      = (const float*)d_in[19];
    const float* ln_g         = (const float*)d_in[20];
    const float* ln_b         = (const float*)d_in[21];
    const float* dec_W        = (const float*)d_in[22];
    float* out = (float*)d_out;

    int total = VV * PP + VV * HH + 2 * PP * HH + PHD * HH + PHD * 2 * HH;
    precompute_kernel<<<(total + 255) / 256, 256>>>(
        emb, sel_W, bind_W1, succ_W1, patch_values, phase_embed, router_W);

    spike_recurrence_kernel<<<BB / BT, NTH>>>(
        input_ids, sel_W, sel_b,
        bind_W1, bind_b1, bind_W2, bind_b2,
        router_b,
        succ_W1, succ_b1, succ_W2, succ_b2,
        gate_W1, gate_b1, gate_W2, gate_b2,
        ln_g, ln_b, out);

    const float* hidden = out + (size_t)BB * SSL * VV;
    decoder_kernel<<<(BB * SSL) / DROWS, DTH>>>(hidden, dec_W, out);
}

// round 10
// speedup vs baseline: 2.6058x; 2.6058x over previous
#include <cuda_runtime.h>
#include <math.h>
#include <cstdint>

#define BB  512
#define SSL 128
#define HH  192
#define VV  256
#define PP  64
#define PHD 16
#define BT  4
#define NTH 384

typedef unsigned long long u64;

// Precomputed folded weights
__device__ float TB_SEL[VV][PP];    // emb @ sel_W[0:192]
__device__ float TB_BIND[VV][HH];   // emb @ bind_W1[0:192]
__device__ float M1[PP][HH];        // patch_values @ bind_W1[192:384]
__device__ float M2[PP][HH];        // patch_values @ succ_W1[192:384]
__device__ float M3[PHD][HH];       // phase_embed  @ succ_W1[384:576]

struct SMLayout {
    float prevb[HH][BT];
    float sec  [HH][BT];
    float succ [HH][BT];
    float htmp [HH][BT];
    float tsel [PP][BT];
    float tbind[HH][BT];
    float pwb  [PP][BT];
    float phwb [PHD][BT];
    float rlog [PHD][BT];
    float4 partbuf[NTH][4];
    float gatev[BT];
    float lnmean[BT], lnrstd[BT];
    int   sidx[BT][SSL];
};

__device__ __forceinline__ float gelu_exact(float x) {
    return 0.5f * x * (1.0f + erff(x * 0.70710678118654752440f));
}
__device__ __forceinline__ float sigmoidf_(float x) {
    return 1.0f / (1.0f + expf(-x));
}
__device__ __forceinline__ u64 ffma2u(u64 a, u64 b, u64 c) {
    u64 d;
    asm("fma.rn.f32x2 %0, %1, %2, %3;" : "=l"(d) : "l"(a), "l"(b), "l"(c));
    return d;
}
__device__ __forceinline__ u64 dup2(float w) {
    u64 d;
    asm("mov.b64 %0, {%1, %1};" : "=l"(d) : "f"(w));
    return d;
}

// 4 cols x 4 rows tile; rows held as 2 f32x2 pairs per column. Contiguous K.
template<int NIT>
__device__ __forceinline__ void seg2(
    u64 (&ac)[4][2],
    const float (*__restrict__ X)[BT], const float* __restrict__ W,
    int xrow0, int wrow0, int Ns, int c0)
{
    #pragma unroll 8
    for (int k = 0; k < NIT; ++k) {
        float4 w = *(const float4*)(W + (size_t)(wrow0 + k) * Ns + c0);
        ulonglong2 x = *(const ulonglong2*)&X[xrow0 + k][0];
        u64 w0 = dup2(w.x), w1 = dup2(w.y), w2 = dup2(w.z), w3 = dup2(w.w);
        ac[0][0] = ffma2u(w0, x.x, ac[0][0]); ac[0][1] = ffma2u(w0, x.y, ac[0][1]);
        ac[1][0] = ffma2u(w1, x.x, ac[1][0]); ac[1][1] = ffma2u(w1, x.y, ac[1][1]);
        ac[2][0] = ffma2u(w2, x.x, ac[2][0]); ac[2][1] = ffma2u(w2, x.y, ac[2][1]);
        ac[3][0] = ffma2u(w3, x.x, ac[3][0]); ac[3][1] = ffma2u(w3, x.y, ac[3][1]);
    }
}

#define PART_STORE()                                                \
    _Pragma("unroll")                                               \
    for (int c = 0; c < 4; ++c) {                                   \
        float4 f;                                                   \
        ((u64*)&f)[0] = ac[c][0]; ((u64*)&f)[1] = ac[c][1];         \
        s->partbuf[t][c] = f;                                       \
    }

// spread reduce: 2 threads per column (float2 halves); col = t>>1, h = t&1
#define REDUCE2(NGP, PCH, COL, H)                                           \
    int gg = (COL) >> 2, cc = (COL) & 3;                                    \
    float2 sv = *(const float2*)((const float*)&s->partbuf[gg][cc] + 2*(H));\
    _Pragma("unroll 8")                                                     \
    for (int pp = 1; pp < (PCH); ++pp) {                                    \
        float2 v = *(const float2*)((const float*)&s->partbuf[pp * (NGP) + gg][cc] + 2*(H)); \
        sv.x += v.x; sv.y += v.y;                                           \
    }

// ---------------- precompute kernel ----------------------------------------
__global__ void precompute_kernel(
    const float* __restrict__ emb, const float* __restrict__ sel_W,
    const float* __restrict__ bind_W1, const float* __restrict__ succ_W1,
    const float* __restrict__ patch_values, const float* __restrict__ phase_embed)
{
    int idx = blockIdx.x * blockDim.x + threadIdx.x;
    const int N0 = VV * PP;
    const int N1 = N0 + VV * HH;
    const int N2 = N1 + PP * HH;
    const int N3 = N2 + PP * HH;
    const int N4 = N3 + PHD * HH;
    if (idx < N0) {
        int v = idx / PP, c = idx % PP;
        float acc = 0.f;
        for (int k = 0; k < HH; ++k) acc = fmaf(emb[v * HH + k], sel_W[k * PP + c], acc);
        TB_SEL[v][c] = acc;
    } else if (idx < N1) {
        int i = idx - N0, v = i / HH, c = i % HH;
        float acc = 0.f;
        for (int k = 0; k < HH; ++k) acc = fmaf(emb[v * HH + k], bind_W1[k * HH + c], acc);
        TB_BIND[v][c] = acc;
    } else if (idx < N2) {
        int i = idx - N1, p = i / HH, c = i % HH;
        float acc = 0.f;
        for (int k = 0; k < HH; ++k) acc = fmaf(patch_values[p * HH + k], bind_W1[(HH + k) * HH + c], acc);
        M1[p][c] = acc;
    } else if (idx < N3) {
        int i = idx - N2, p = i / HH, c = i % HH;
        float acc = 0.f;
        for (int k = 0; k < HH; ++k) acc = fmaf(patch_values[p * HH + k], succ_W1[(HH + k) * HH + c], acc);
        M2[p][c] = acc;
    } else if (idx < N4) {
        int i = idx - N3, q = i / HH, c = i % HH;
        float acc = 0.f;
        for (int k = 0; k < HH; ++k) acc = fmaf(phase_embed[q * HH + k], succ_W1[(2 * HH + k) * HH + c], acc);
        M3[q][c] = acc;
    }
}

// ---------------- decoder kernel -------------------------------------------
#define DROWS 64
#define DTH   512
__global__ __launch_bounds__(DTH, 1)
void decoder_kernel(const float* __restrict__ hidden,
                    const float* __restrict__ dec_W,
                    float* __restrict__ logits)
{
    __shared__ float hid[HH][DROWS];
    const int t = threadIdx.x;
    const size_t row0 = (size_t)blockIdx.x * DROWS;

    for (int i = t; i < DROWS * (HH / 4); i += DTH) {
        int r = i / (HH / 4), kq = i % (HH / 4);
        float4 v = *(const float4*)&hidden[(row0 + r) * HH + 4 * kq];
        hid[4 * kq + 0][r] = v.x; hid[4 * kq + 1][r] = v.y;
        hid[4 * kq + 2][r] = v.z; hid[4 * kq + 3][r] = v.w;
    }
    __syncthreads();

    const int cg = t % 64, rg = t / 64;
    const int c0 = 4 * cg, r0 = 8 * rg;
    u64 ac[4][4] = {};
    #pragma unroll 4
    for (int k = 0; k < HH; ++k) {
        float4 w = *(const float4*)&dec_W[(size_t)k * VV + c0];
        ulonglong2 xa = *(const ulonglong2*)&hid[k][r0];
        ulonglong2 xb = *(const ulonglong2*)&hid[k][r0 + 4];
        u64 w0 = dup2(w.x), w1 = dup2(w.y), w2 = dup2(w.z), w3 = dup2(w.w);
        ac[0][0] = ffma2u(w0, xa.x, ac[0][0]); ac[0][1] = ffma2u(w0, xa.y, ac[0][1]);
        ac[0][2] = ffma2u(w0, xb.x, ac[0][2]); ac[0][3] = ffma2u(w0, xb.y, ac[0][3]);
        ac[1][0] = ffma2u(w1, xa.x, ac[1][0]); ac[1][1] = ffma2u(w1, xa.y, ac[1][1]);
        ac[1][2] = ffma2u(w1, xb.x, ac[1][2]); ac[1][3] = ffma2u(w1, xb.y, ac[1][3]);
        ac[2][0] = ffma2u(w2, xa.x, ac[2][0]); ac[2][1] = ffma2u(w2, xa.y, ac[2][1]);
        ac[2][2] = ffma2u(w2, xb.x, ac[2][2]); ac[2][3] = ffma2u(w2, xb.y, ac[2][3]);
        ac[3][0] = ffma2u(w3, xa.x, ac[3][0]); ac[3][1] = ffma2u(w3, xa.y, ac[3][1]);
        ac[3][2] = ffma2u(w3, xb.x, ac[3][2]); ac[3][3] = ffma2u(w3, xb.y, ac[3][3]);
    }
    #pragma unroll
    for (int p = 0; p < 4; ++p) {
        #pragma unroll
        for (int j = 0; j < 2; ++j) {
            int r = r0 + 2 * p + j;
            float4 o;
            o.x = ((float*)&ac[0][p])[j]; o.y = ((float*)&ac[1][p])[j];
            o.z = ((float*)&ac[2][p])[j]; o.w = ((float*)&ac[3][p])[j];
            *(float4*)&logits[(row0 + r) * VV + c0] = o;
        }
    }
}

// ---------------- token-table gather ----------------------------------------
__device__ __forceinline__ void gather_tables(SMLayout* s, int t, int st) {
    int id0 = s->sidx[0][st], id1 = s->sidx[1][st],
        id2 = s->sidx[2][st], id3 = s->sidx[3][st];
    if (t < PP * BT) {
        int c = t % PP, r = t / PP;
        int id = (r == 0) ? id0 : (r == 1) ? id1 : (r == 2) ? id2 : id3;
        s->tsel[c][r] = TB_SEL[id][c];
    }
    for (int i = t; i < HH * BT; i += NTH) {
        int c = i % HH, r = i / HH;
        int id = (r == 0) ? id0 : (r == 1) ? id1 : (r == 2) ? id2 : id3;
        s->tbind[c][r] = TB_BIND[id][c];
    }
}

// ---------------- main recurrence kernel -----------------------------------
__global__ __launch_bounds__(NTH, 1)
void spike_recurrence_kernel(
    const int*   __restrict__ input_ids,
    const float* __restrict__ sel_W,  const float* __restrict__ sel_b,
    const float* __restrict__ bind_W1, const float* __restrict__ bind_b1,
    const float* __restrict__ bind_W2, const float* __restrict__ bind_b2,
    const float* __restrict__ router_W, const float* __restrict__ router_b,
    const float* __restrict__ succ_W1, const float* __restrict__ succ_b1,
    const float* __restrict__ succ_W2, const float* __restrict__ succ_b2,
    const float* __restrict__ gate_W1, const float* __restrict__ gate_b1,
    const float* __restrict__ gate_W2, const float* __restrict__ gate_b2,
    const float* __restrict__ ln_g,   const float* __restrict__ ln_b,
    float* __restrict__ out)
{
    extern __shared__ __align__(16) char smraw[];
    SMLayout* s = (SMLayout*)smraw;

    const int t    = threadIdx.x;
    const int lane = t & 31;
    const int warp = t >> 5;
    const int bbase = blockIdx.x * BT;
    const int col2 = t >> 1, hh2 = t & 1;

    for (int i = t; i < BT * SSL; i += NTH) {
        int r = i / SSL, ss = i % SSL;
        s->sidx[r][ss] = input_ids[(bbase + r) * SSL + ss];
    }
    if (t < HH) *(float4*)&s->prevb[t][0] = make_float4(0.f, 0.f, 0.f, 0.f);
    __syncthreads();
    gather_tables(s, t, 0);
    __syncthreads();

    const size_t OFF_HID = (size_t)BB * SSL * VV;
    const size_t OFF_PW  = OFF_HID + (size_t)BB * SSL * HH;
    const size_t OFF_PHW = OFF_PW  + (size_t)BB * SSL * PP;
    const size_t OFF_GT  = OFF_PHW + (size_t)BB * SSL * PHD;

    const float* selWp  = sel_W  + HH * PP;
    const float* bindWp = bind_W1 + 2 * (size_t)HH * HH;
    const float* gateWp = gate_W1 + (size_t)HH * HH;
    const float* routWp = router_W + (size_t)HH * PHD;

    for (int st = 0; st < SSL; ++st) {
        // ---- sel GEMM: prev @ selWp  (N=64, NG=16, P=24) ------------------
        {
            int g = t % 16, p = t / 16, c0 = 4 * g;
            u64 ac[4][2] = {};
            seg2<8>(ac, s->prevb, selWp, p * 8, p * 8, PP, c0);
            PART_STORE();
        }
        __syncthreads();
        if (t < 2 * PP) {
            REDUCE2(16, 24, col2, hh2);
            float2 tv = *(const float2*)&s->tsel[col2][2 * hh2];
            float bias = sel_b[col2];
            sv.x += tv.x + bias; sv.y += tv.y + bias;
            *(float2*)&s->pwb[col2][2 * hh2] = sv;
        }
        __syncthreads();
        if (warp < BT) {   // softmax over 64
            int r = warp;
            float v0 = s->pwb[lane][r], v1 = s->pwb[lane + 32][r];
            float m = fmaxf(v0, v1);
            #pragma unroll
            for (int o = 16; o > 0; o >>= 1) m = fmaxf(m, __shfl_xor_sync(0xffffffffu, m, o));
            float e0 = expf(v0 - m), e1 = expf(v1 - m);
            float smv = e0 + e1;
            #pragma unroll
            for (int o = 16; o > 0; o >>= 1) smv += __shfl_xor_sync(0xffffffffu, smv, o);
            float inv = 1.0f / smv;
            e0 *= inv; e1 *= inv;
            s->pwb[lane][r] = e0; s->pwb[lane + 32][r] = e1;
            size_t ob = OFF_PW + ((size_t)(bbase + r) * SSL + st) * PP;
            out[ob + lane] = e0; out[ob + lane + 32] = e1;
        }
        __syncthreads();

        // ---- bind1: prev @ bindWp + pw @ M1 + tbind -> gelu ---------------
        {
            int g = t % 48, p = t / 48, c0 = 4 * g;
            u64 ac[4][2] = {};
            seg2<24>(ac, s->prevb, bindWp,    p * 24, p * 24, HH, c0);
            seg2<8> (ac, s->pwb,   &M1[0][0], p * 8,  p * 8,  HH, c0);
            PART_STORE();
        }
        __syncthreads();
        {
            REDUCE2(48, 8, col2, hh2);
            float2 tv = *(const float2*)&s->tbind[col2][2 * hh2];
            float b1 = bind_b1[col2];
            float2 h;
            h.x = gelu_exact(sv.x + tv.x + b1); h.y = gelu_exact(sv.y + tv.y + b1);
            *(float2*)&s->htmp[col2][2 * hh2] = h;
        }
        __syncthreads();

        // ---- bind2 -> tanh -> sec -----------------------------------------
        {
            int g = t % 48, p = t / 48, c0 = 4 * g;
            u64 ac[4][2] = {};
            seg2<24>(ac, s->htmp, bind_W2, p * 24, p * 24, HH, c0);
            PART_STORE();
        }
        __syncthreads();
        {
            REDUCE2(48, 8, col2, hh2);
            float b2 = bind_b2[col2];
            float2 h;
            h.x = tanhf(sv.x + b2); h.y = tanhf(sv.y + b2);
            *(float2*)&s->sec[col2][2 * hh2] = h;
        }
        __syncthreads();

        // ---- router: [sec,prev] @ router_W  (N=16, NG=4, P=96) -------------
        {
            int g = t % 4, p = t / 4, c0 = 4 * g;
            u64 ac[4][2] = {};
            seg2<2>(ac, s->sec,   router_W, p * 2, p * 2, PHD, c0);
            seg2<2>(ac, s->prevb, routWp,   p * 2, p * 2, PHD, c0);
            PART_STORE();
        }
        __syncthreads();
        if (t < 2 * PHD) {
            REDUCE2(4, 96, col2, hh2);
            float bias = router_b[col2];
            sv.x += bias; sv.y += bias;
            *(float2*)&s->rlog[col2][2 * hh2] = sv;
        }
        __syncthreads();
        if (t < BT) {
            int r = t;
            float m = -1e30f;
            #pragma unroll
            for (int c = 0; c < PHD; ++c) m = fmaxf(m, s->rlog[c][r]);
            float smv = 0.f;
            float e[PHD];
            #pragma unroll
            for (int c = 0; c < PHD; ++c) { e[c] = expf(s->rlog[c][r] - m); smv += e[c]; }
            float inv = 1.0f / smv;
            size_t ob = OFF_PHW + ((size_t)(bbase + r) * SSL + st) * PHD;
            #pragma unroll
            for (int c = 0; c < PHD; ++c) {
                float v = e[c] * inv;
                s->phwb[c][r] = v;
                out[ob + c] = v;
            }
        }
        __syncthreads();

        // ---- succ1: sec @ W + pw @ M2 + phw @ M3 -> gelu --------------------
        {
            int g = t % 48, p = t / 48, c0 = 4 * g;
            u64 ac[4][2] = {};
            seg2<24>(ac, s->sec,  succ_W1,   p * 24, p * 24, HH, c0);
            seg2<8> (ac, s->pwb,  &M2[0][0], p * 8,  p * 8,  HH, c0);
            seg2<2> (ac, s->phwb, &M3[0][0], p * 2,  p * 2,  HH, c0);
            PART_STORE();
        }
        __syncthreads();
        {
            REDUCE2(48, 8, col2, hh2);
            float b1 = succ_b1[col2];
            float2 h;
            h.x = gelu_exact(sv.x + b1); h.y = gelu_exact(sv.y + b1);
            *(float2*)&s->htmp[col2][2 * hh2] = h;
        }
        __syncthreads();

        // ---- succ2 -> tanh -> succ ------------------------------------------
        {
            int g = t % 48, p = t / 48, c0 = 4 * g;
            u64 ac[4][2] = {};
            seg2<24>(ac, s->htmp, succ_W2, p * 24, p * 24, HH, c0);
            PART_STORE();
        }
        __syncthreads();
        {
            REDUCE2(48, 8, col2, hh2);
            float b2 = succ_b2[col2];
            float2 h;
            h.x = tanhf(sv.x + b2); h.y = tanhf(sv.y + b2);
            *(float2*)&s->succ[col2][2 * hh2] = h;
        }
        __syncthreads();

        // ---- gate: [succ,prev] @ gate_W1 -> gelu * gate_W2 -------------------
        {
            int g = t % 48, p = t / 48, c0 = 4 * g;
            u64 ac[4][2] = {};
            seg2<24>(ac, s->succ,  gate_W1, p * 24, p * 24, HH, c0);
            seg2<24>(ac, s->prevb, gateWp,  p * 24, p * 24, HH, c0);
            PART_STORE();
        }
        __syncthreads();
        {
            REDUCE2(48, 8, col2, hh2);
            float b1 = gate_b1[col2];
            float w2 = gate_W2[col2];
            float2 h;
            h.x = gelu_exact(sv.x + b1) * w2; h.y = gelu_exact(sv.y + b1) * w2;
            *(float2*)&s->htmp[col2][2 * hh2] = h;
        }
        __syncthreads();

        // ---- MERGED: gate rowsum -> sigmoid -> LN stats (warps 0-3) ----------
        if (warp < BT) {
            int r = warp;
            float sg = 0.f;
            #pragma unroll
            for (int j = 0; j < 6; ++j) sg += s->htmp[lane + 32 * j][r];
            #pragma unroll
            for (int o = 16; o > 0; o >>= 1) sg += __shfl_xor_sync(0xffffffffu, sg, o);
            float gv = sigmoidf_(sg + gate_b2[0]);   // all lanes have it
            if (lane == 0) {
                s->gatev[r] = gv;
                out[OFF_GT + (size_t)(bbase + r) * SSL + st] = gv;
            }
            // LN stats with on-the-fly blend
            float smv = 0.f, sq = 0.f;
            #pragma unroll
            for (int j = 0; j < 6; ++j) {
                int c = lane + 32 * j;
                float v = gv * s->succ[c][r] + (1.f - gv) * s->prevb[c][r];
                smv += v; sq += v * v;
            }
            #pragma unroll
            for (int o = 16; o > 0; o >>= 1) {
                smv += __shfl_xor_sync(0xffffffffu, smv, o);
                sq  += __shfl_xor_sync(0xffffffffu, sq, o);
            }
            if (lane == 0) {
                float mean = smv * (1.0f / HH);
                float var  = sq * (1.0f / HH) - mean * mean;
                s->lnmean[r] = mean;
                s->lnrstd[r] = rsqrtf(var + 1e-5f);
            }
        }
        __syncthreads();

        // ---- blend recompute + LN write + prefetch next tables ----------------
        if (t < HH) {
            float g = ln_g[t], bb = ln_b[t];
            float4 svv = *(const float4*)&s->succ[t][0];
            float4 pv  = *(const float4*)&s->prevb[t][0];
            float g0 = s->gatev[0], g1 = s->gatev[1], g2 = s->gatev[2], g3 = s->gatev[3];
            float h0 = g0 * svv.x + (1.f - g0) * pv.x;
            float h1 = g1 * svv.y + (1.f - g1) * pv.y;
            float h2 = g2 * svv.z + (1.f - g2) * pv.z;
            float h3 = g3 * svv.w + (1.f - g3) * pv.w;
            float4 o;
            o.x = (h0 - s->lnmean[0]) * s->lnrstd[0] * g + bb;
            o.y = (h1 - s->lnmean[1]) * s->lnrstd[1] * g + bb;
            o.z = (h2 - s->lnmean[2]) * s->lnrstd[2] * g + bb;
            o.w = (h3 - s->lnmean[3]) * s->lnrstd[3] * g + bb;
            *(float4*)&s->prevb[t][0] = o;
            #pragma unroll
            for (int r = 0; r < BT; ++r)
                out[OFF_HID + ((size_t)(bbase + r) * SSL + st) * HH + t] =
                    (r == 0) ? o.x : (r == 1) ? o.y : (r == 2) ? o.z : o.w;
        }
        if (st + 1 < SSL) gather_tables(s, t, st + 1);
        __syncthreads();
    }
}

extern "C" void kernel_launch(void* const* d_in, const int* in_sizes, int n_in,
                              void* d_out, int out_size) {
    const int*   input_ids    = (const int*)  d_in[0];
    const float* emb          = (const float*)d_in[1];
    const float* sel_W        = (const float*)d_in[2];
    const float* sel_b        = (const float*)d_in[3];
    const float* patch_values = (const float*)d_in[4];
    const float* bind_W1      = (const float*)d_in[5];
    const float* bind_b1      = (const float*)d_in[6];
    const float* bind_W2      = (const float*)d_in[7];
    const float* bind_b2      = (const float*)d_in[8];
    const float* phase_embed  = (const float*)d_in[9];
    const float* router_W     = (const float*)d_in[10];
    const float* router_b     = (const float*)d_in[11];
    const float* succ_W1      = (const float*)d_in[12];
    const float* succ_b1      = (const float*)d_in[13];
    const float* succ_W2      = (const float*)d_in[14];
    const float* succ_b2      = (const float*)d_in[15];
    const float* gate_W1      = (const float*)d_in[16];
    const float* gate_b1      = (const float*)d_in[17];
    const float* gate_W2      = (const float*)d_in[18];
    const float* gate_b2      = (const float*)d_in[19];
    const float* ln_g         = (const float*)d_in[20];
    const float* ln_b         = (const float*)d_in[21];
    const float* dec_W        = (const float*)d_in[22];
    float* out = (float*)d_out;

    int total = VV * PP + VV * HH + 2 * PP * HH + PHD * HH;
    precompute_kernel<<<(total + 255) / 256, 256>>>(
        emb, sel_W, bind_W1, succ_W1, patch_values, phase_embed);

    cudaFuncSetAttribute(spike_recurrence_kernel,
                         cudaFuncAttributeMaxDynamicSharedMemorySize,
                         (int)sizeof(SMLayout));

    spike_recurrence_kernel<<<BB / BT, NTH, sizeof(SMLayout)>>>(
        input_ids, sel_W, sel_b,
        bind_W1, bind_b1, bind_W2, bind_b2,
        router_W, router_b,
        succ_W1, succ_b1, succ_W2, succ_b2,
        gate_W1, gate_b1, gate_W2, gate_b2,
        ln_g, ln_b, out);

    const float* hidden = out + (size_t)BB * SSL * VV;
    decoder_kernel<<<(BB * SSL) / DROWS, DTH>>>(hidden, dec_W, out);
}